// round 5
// baseline (speedup 1.0000x reference)
#include <cuda_runtime.h>
#include <cuda_bf16.h>
#include <cstdint>

#define DEV_INLINE __device__ __forceinline__

// ---------------------------------------------------------------------------
// Problem constants
// ---------------------------------------------------------------------------
constexpr int M_TOTAL = 4096;    // B*T
constexpr int N_TOTAL = 32000;   // C
constexpr int K_TOTAL = 256;     // D

constexpr int TM = 128;
constexpr int TN = 128;
constexpr int KC = 128;                       // K chunk (fp8 elems = bytes)
constexpr int NKC = K_TOTAL / KC;             // 2 chunks

// quantization scales (avoid e4m3 subnormals; fold out in epilogue)
constexpr float XSCALE = 8.0f;
constexpr float WSCALE = 64.0f;
constexpr float ACC_INV = 1.0f / (XSCALE * WSCALE);   // 1/512

// smem: 2 pipeline slots, each = A chunk (16KB) + B chunk (16KB)
constexpr int SMEM_SLOT   = 32768;
constexpr int SMEM_B_OFF  = 16384;
constexpr int SMEM_C0     = 2 * SMEM_SLOT;            // 65536: 128 floats
constexpr int SMEM_X0     = SMEM_C0 + 512;            // 66048: 128 floats
constexpr int SMEM_TOTAL  = SMEM_X0 + 512;            // 66560 bytes

// ---------------------------------------------------------------------------
// Scratch (device globals: allocation-free rule)
// ---------------------------------------------------------------------------
__device__ uint8_t g_xq[(size_t)M_TOTAL * K_TOTAL];   // 1 MB  e4m3, x*8
__device__ float   g_x0[M_TOTAL];
__device__ uint8_t g_wq[(size_t)N_TOTAL * K_TOTAL];   // 8 MB  e4m3, w*64
__device__ float   g_c0[N_TOTAL];

// ---------------------------------------------------------------------------
// PTX helpers (base sm_103-safe: cp.async / ldmatrix / mma.sync fp8)
// ---------------------------------------------------------------------------
DEV_INLINE uint32_t smem_to_u32(const void* smem_ptr) {
    uint32_t addr;
    asm("{ .reg .u64 tmp; cvta.to.shared.u64 tmp, %1; cvt.u32.u64 %0, tmp; }"
        : "=r"(addr) : "l"(smem_ptr));
    return addr;
}

DEV_INLINE void cp_async16(uint32_t dst_smem, const void* src) {
    asm volatile("cp.async.cg.shared.global [%0], [%1], 16;"
                 :: "r"(dst_smem), "l"(src));
}
DEV_INLINE void cp_async_commit() {
    asm volatile("cp.async.commit_group;" ::: "memory");
}
template <int N>
DEV_INLINE void cp_async_wait() {
    asm volatile("cp.async.wait_group %0;" :: "n"(N) : "memory");
}

DEV_INLINE void ldmatrix_x4(uint32_t& r0, uint32_t& r1, uint32_t& r2, uint32_t& r3,
                            uint32_t addr) {
    asm volatile("ldmatrix.sync.aligned.m8n8.x4.shared.b16 {%0,%1,%2,%3}, [%4];"
                 : "=r"(r0), "=r"(r1), "=r"(r2), "=r"(r3) : "r"(addr));
}

// fp8 e4m3 MMA: m16n8k32, fp32 accumulate
DEV_INLINE void mma_fp8(float* d, const uint32_t* a, uint32_t b0, uint32_t b1) {
    asm volatile(
        "mma.sync.aligned.m16n8k32.row.col.f32.e4m3.e4m3.f32 "
        "{%0,%1,%2,%3}, {%4,%5,%6,%7}, {%8,%9}, {%0,%1,%2,%3};"
        : "+f"(d[0]), "+f"(d[1]), "+f"(d[2]), "+f"(d[3])
        : "r"(a[0]), "r"(a[1]), "r"(a[2]), "r"(a[3]), "r"(b0), "r"(b1));
}

// pack two floats -> e4m3x2 (byte0 = lo, byte1 = hi)
DEV_INLINE uint16_t pack_e4m3x2(float hi, float lo) {
    uint16_t v;
    asm("cvt.rn.satfinite.e4m3x2.f32 %0, %1, %2;" : "=h"(v) : "f"(hi), "f"(lo));
    return v;
}

// ---------------------------------------------------------------------------
// Prep kernel: fp32 -> e4m3 (scaled) + exact fp32 Lorentz norms
// blocks [0, 512): x rows (8 rows/block); blocks [512, 4512): w rows
// ---------------------------------------------------------------------------
__global__ void __launch_bounds__(256) prep_kernel(const float* __restrict__ x,
                                                   const float* __restrict__ w) {
    const int lane = threadIdx.x & 31;
    if (blockIdx.x < 512) {
        int gw = (blockIdx.x * 256 + threadIdx.x) >> 5;   // 0..4095
        const float4* r = reinterpret_cast<const float4*>(x + (size_t)gw * K_TOTAL);
        float4 f0 = r[lane * 2];
        float4 f1 = r[lane * 2 + 1];
        float s = f0.x * f0.x + f0.y * f0.y + f0.z * f0.z + f0.w * f0.w
                + f1.x * f1.x + f1.y * f1.y + f1.z * f1.z + f1.w * f1.w;
        uint32_t lo = (uint32_t)pack_e4m3x2(f0.y * XSCALE, f0.x * XSCALE)
                    | ((uint32_t)pack_e4m3x2(f0.w * XSCALE, f0.z * XSCALE) << 16);
        uint32_t hi = (uint32_t)pack_e4m3x2(f1.y * XSCALE, f1.x * XSCALE)
                    | ((uint32_t)pack_e4m3x2(f1.w * XSCALE, f1.z * XSCALE) << 16);
        *reinterpret_cast<uint2*>(g_xq + (size_t)gw * K_TOTAL + lane * 8) =
            make_uint2(lo, hi);
        #pragma unroll
        for (int o = 16; o; o >>= 1) s += __shfl_xor_sync(0xFFFFFFFFu, s, o);
        if (lane == 0) g_x0[gw] = sqrtf(1.0f + s);
    } else {
        int gw = ((blockIdx.x - 512) * 256 + threadIdx.x) >> 5;  // 0..31999
        const float* r = w + (size_t)gw * 257 + 1 + lane * 8;
        float a0 = r[0], a1 = r[1], a2 = r[2], a3 = r[3];
        float a4 = r[4], a5 = r[5], a6 = r[6], a7 = r[7];
        float s = a0 * a0 + a1 * a1 + a2 * a2 + a3 * a3
                + a4 * a4 + a5 * a5 + a6 * a6 + a7 * a7;
        uint32_t lo = (uint32_t)pack_e4m3x2(a1 * WSCALE, a0 * WSCALE)
                    | ((uint32_t)pack_e4m3x2(a3 * WSCALE, a2 * WSCALE) << 16);
        uint32_t hi = (uint32_t)pack_e4m3x2(a5 * WSCALE, a4 * WSCALE)
                    | ((uint32_t)pack_e4m3x2(a7 * WSCALE, a6 * WSCALE) << 16);
        *reinterpret_cast<uint2*>(g_wq + (size_t)gw * K_TOTAL + lane * 8) =
            make_uint2(lo, hi);
        #pragma unroll
        for (int o = 16; o; o >>= 1) s += __shfl_xor_sync(0xFFFFFFFFu, s, o);
        if (lane == 0) g_c0[gw] = sqrtf(1.0f + s);
    }
}

// ---------------------------------------------------------------------------
// GEMM helpers
// ---------------------------------------------------------------------------
DEV_INLINE float neg_acosh_clip(float v) {
    v = fmaxf(v, 1.0f + 1e-6f);
    float t = fmaf(v, v, -1.0f);
    float s;
    asm("sqrt.approx.f32 %0, %1;" : "=f"(s) : "f"(t));
    float w = v + s;
    float l;
    asm("lg2.approx.f32 %0, %1;" : "=f"(l) : "f"(w));
    return l * -0.6931471805599453f;   // -ln(w)
}

// load A+B chunk kc (128 rows x 128 fp8 each) into pipeline slot `slot`
DEV_INLINE void load_chunk(uint32_t sb, int slot, int m_base, int n_base, int kc,
                           int tid) {
    const uint32_t abase = sb + slot * SMEM_SLOT;
    const uint32_t bbase = abase + SMEM_B_OFF;
    const size_t koff = (size_t)kc * KC;
    #pragma unroll
    for (int it = 0; it < 4; it++) {
        int idx = tid + it * 256;      // 0..1023
        int row = idx >> 3;            // 0..127
        int c16 = idx & 7;             // 16B column within 128B row
        uint32_t col = (uint32_t)(c16 * 16) ^ (uint32_t)((row & 7) << 4);
        cp_async16(abase + row * 128 + col,
                   g_xq + (size_t)(m_base + row) * K_TOTAL + koff + c16 * 16);
    }
    #pragma unroll
    for (int it = 0; it < 4; it++) {
        int idx = tid + it * 256;
        int row = idx >> 3;
        int c16 = idx & 7;
        uint32_t col = (uint32_t)(c16 * 16) ^ (uint32_t)((row & 7) << 4);
        cp_async16(bbase + row * 128 + col,
                   g_wq + (size_t)(n_base + row) * K_TOTAL + koff + c16 * 16);
    }
}

struct MmaCtx {
    int a_row; uint32_t a_khalf;
    int b_row; uint32_t b_khalf;
    uint32_t rsw;
};

// one chunk = 128 fp8 K = 4 k-steps of 32
DEV_INLINE void mma_chunk(uint32_t sb, int slot, const MmaCtx& c,
                          float acc[2][8][4]) {
    const uint32_t abase = sb + slot * SMEM_SLOT;
    const uint32_t bbase = abase + SMEM_B_OFF;
    #pragma unroll
    for (int ks = 0; ks < 4; ks++) {
        const uint32_t kbyte = (uint32_t)(ks * 32);
        uint32_t a[2][4];
        #pragma unroll
        for (int mf = 0; mf < 2; mf++) {
            uint32_t addr = abase + (uint32_t)(c.a_row + mf * 16) * 128 +
                            ((kbyte + c.a_khalf) ^ c.rsw);
            ldmatrix_x4(a[mf][0], a[mf][1], a[mf][2], a[mf][3], addr);
        }
        #pragma unroll
        for (int nf2 = 0; nf2 < 4; nf2++) {
            uint32_t b0, b1, b2, b3;
            uint32_t addr = bbase + (uint32_t)(c.b_row + nf2 * 16) * 128 +
                            ((kbyte + c.b_khalf) ^ c.rsw);
            ldmatrix_x4(b0, b1, b2, b3, addr);
            #pragma unroll
            for (int mf = 0; mf < 2; mf++) {
                mma_fp8(acc[mf][nf2 * 2 + 0], a[mf], b0, b1);
                mma_fp8(acc[mf][nf2 * 2 + 1], a[mf], b2, b3);
            }
        }
    }
}

// ---------------------------------------------------------------------------
// Main GEMM + arccosh epilogue.
// grid = (250, 32), block = 256 (8 warps; warp tile 32x64: 4 M x 2 N).
// 2-chunk cp.async pipeline (K=256 fp8), 2 barriers per tile, 2 CTAs/SM.
// ---------------------------------------------------------------------------
__global__ void __launch_bounds__(256, 2) lorentz_gemm_kernel(float* __restrict__ out) {
    extern __shared__ char smem[];
    const uint32_t sb = smem_to_u32(smem);
    const int tid = threadIdx.x;
    const int wid = tid >> 5;
    const int lid = tid & 31;
    const int m_base = blockIdx.y * TM;
    const int n_base = blockIdx.x * TN;

    // warp tile position: 4 warps along M, 2 along N
    const int m_off = (wid & 3) * 32;
    const int n_off = (wid >> 2) * 64;

    // ldmatrix lane decomposition (16B granules; identical to bf16 layout)
    const int g = lid >> 3;
    const int r = lid & 7;
    MmaCtx c;
    c.rsw = (uint32_t)(r << 4);
    c.a_row = m_off + (g & 1) * 8 + r;
    c.a_khalf = (uint32_t)((g >> 1) * 16);
    c.b_row = n_off + (g >> 1) * 8 + r;
    c.b_khalf = (uint32_t)((g & 1) * 16);

    float* const s_c0 = reinterpret_cast<float*>(smem + SMEM_C0);
    float* const s_x0 = reinterpret_cast<float*>(smem + SMEM_X0);

    // prologue: both K chunks in flight
    load_chunk(sb, 0, m_base, n_base, 0, tid);
    cp_async_commit();
    load_chunk(sb, 1, m_base, n_base, 1, tid);
    cp_async_commit();

    if (tid < 128) s_c0[tid] = g_c0[n_base + tid];
    else           s_x0[tid - 128] = g_x0[m_base + tid - 128];

    float acc[2][8][4] = {};

    cp_async_wait<1>();
    __syncthreads();
    mma_chunk(sb, 0, c, acc);

    cp_async_wait<0>();
    __syncthreads();
    mma_chunk(sb, 1, c, acc);

    // ---- epilogue (streaming stores, MUFU acosh, unscale by 1/512) ----
    const int tr = lid >> 2;
    const int tc = (lid & 3) * 2;

    #pragma unroll
    for (int mf = 0; mf < 2; mf++) {
        const int rl = m_off + mf * 16 + tr;
        const float x0a = s_x0[rl];
        const float x0b = s_x0[rl + 8];
        float* out_lo = out + (size_t)(m_base + rl) * N_TOTAL + n_base;
        float* out_hi = out_lo + (size_t)8 * N_TOTAL;
        #pragma unroll
        for (int nf = 0; nf < 8; nf++) {
            const int col = n_off + nf * 8 + tc;
            const float c0x = s_c0[col];
            const float c0y = s_c0[col + 1];
            const float* a4 = acc[mf][nf];
            float2 lo, hi;
            lo.x = neg_acosh_clip(fmaf(-a4[0], ACC_INV, x0a * c0x));
            lo.y = neg_acosh_clip(fmaf(-a4[1], ACC_INV, x0a * c0y));
            hi.x = neg_acosh_clip(fmaf(-a4[2], ACC_INV, x0b * c0x));
            hi.y = neg_acosh_clip(fmaf(-a4[3], ACC_INV, x0b * c0y));
            __stcs(reinterpret_cast<float2*>(out_lo + col), lo);
            __stcs(reinterpret_cast<float2*>(out_hi + col), hi);
        }
    }
}

// ---------------------------------------------------------------------------
// Launch
// ---------------------------------------------------------------------------
extern "C" void kernel_launch(void* const* d_in, const int* in_sizes, int n_in,
                              void* d_out, int out_size) {
    const float* x = (const float*)d_in[0];        // [2,2048,256] fp32
    const float* w = (const float*)d_in[1];        // [32000,257] fp32
    float* out = (float*)d_out;                    // [2,2048,32000] fp32
    (void)in_sizes; (void)n_in; (void)out_size;

    cudaFuncSetAttribute(lorentz_gemm_kernel,
                         cudaFuncAttributeMaxDynamicSharedMemorySize, SMEM_TOTAL);

    prep_kernel<<<4512, 256>>>(x, w);

    dim3 grid(N_TOTAL / TN, M_TOTAL / TM);  // (250, 32)
    lorentz_gemm_kernel<<<grid, 256, SMEM_TOTAL>>>(out);
}

// round 6
// speedup vs baseline: 1.0466x; 1.0466x over previous
#include <cuda_runtime.h>
#include <cuda_bf16.h>
#include <cstdint>

#define DEV_INLINE __device__ __forceinline__

// ---------------------------------------------------------------------------
// Problem constants
// ---------------------------------------------------------------------------
constexpr int M_TOTAL = 4096;    // B*T
constexpr int N_TOTAL = 32000;   // C
constexpr int K_TOTAL = 256;     // D

constexpr int TM = 128;
constexpr int TN = 128;
constexpr int KC = 64;                        // K chunk (bf16 elems)

// smem: 3 pipeline slots, each = A chunk (16KB) + B chunk (16KB)
// epilogue staging buffer (64KB fp32) overlaps slots 0+1
constexpr int SMEM_SLOT   = 32768;
constexpr int SMEM_B_OFF  = 16384;
constexpr int SMEM_C0     = 3 * SMEM_SLOT;            // 98304: 128 floats
constexpr int SMEM_X0     = SMEM_C0 + 512;            // 98816: 128 floats
constexpr int SMEM_TOTAL  = SMEM_X0 + 512;            // 99328 bytes

// ---------------------------------------------------------------------------
// Scratch (device globals: allocation-free rule)
// ---------------------------------------------------------------------------
__device__ __nv_bfloat16 g_xb[(size_t)M_TOTAL * K_TOTAL];  // 2 MB
__device__ float         g_x0[M_TOTAL];
__device__ __nv_bfloat16 g_wb[(size_t)N_TOTAL * K_TOTAL];  // 16 MB
__device__ float         g_c0[N_TOTAL];

// ---------------------------------------------------------------------------
// PTX helpers (base sm_103-safe: cp.async / ldmatrix / mma.sync only)
// ---------------------------------------------------------------------------
DEV_INLINE uint32_t smem_to_u32(const void* smem_ptr) {
    uint32_t addr;
    asm("{ .reg .u64 tmp; cvta.to.shared.u64 tmp, %1; cvt.u32.u64 %0, tmp; }"
        : "=r"(addr) : "l"(smem_ptr));
    return addr;
}

DEV_INLINE void cp_async16(uint32_t dst_smem, const void* src) {
    asm volatile("cp.async.cg.shared.global [%0], [%1], 16;"
                 :: "r"(dst_smem), "l"(src));
}
DEV_INLINE void cp_async_commit() {
    asm volatile("cp.async.commit_group;" ::: "memory");
}
template <int N>
DEV_INLINE void cp_async_wait() {
    asm volatile("cp.async.wait_group %0;" :: "n"(N) : "memory");
}

DEV_INLINE void ldmatrix_x4(uint32_t& r0, uint32_t& r1, uint32_t& r2, uint32_t& r3,
                            uint32_t addr) {
    asm volatile("ldmatrix.sync.aligned.m8n8.x4.shared.b16 {%0,%1,%2,%3}, [%4];"
                 : "=r"(r0), "=r"(r1), "=r"(r2), "=r"(r3) : "r"(addr));
}

DEV_INLINE void mma_16816(float* d, const uint32_t* a, uint32_t b0, uint32_t b1) {
    asm volatile(
        "mma.sync.aligned.m16n8k16.row.col.f32.bf16.bf16.f32 "
        "{%0,%1,%2,%3}, {%4,%5,%6,%7}, {%8,%9}, {%0,%1,%2,%3};"
        : "+f"(d[0]), "+f"(d[1]), "+f"(d[2]), "+f"(d[3])
        : "r"(a[0]), "r"(a[1]), "r"(a[2]), "r"(a[3]), "r"(b0), "r"(b1));
}

// ---------------------------------------------------------------------------
// Prep kernel (merged): fp32 -> bf16 + exact fp32 Lorentz norms
// blocks [0, 512): x rows (8 rows/block); blocks [512, 4512): w rows
// ---------------------------------------------------------------------------
DEV_INLINE uint32_t pack_bf2(float a, float b) {
    __nv_bfloat162 h = __floats2bfloat162_rn(a, b);
    return *reinterpret_cast<uint32_t*>(&h);
}

__global__ void __launch_bounds__(256) prep_kernel(const float* __restrict__ x,
                                                   const float* __restrict__ w) {
    const int lane = threadIdx.x & 31;
    if (blockIdx.x < 512) {
        int gw = (blockIdx.x * 256 + threadIdx.x) >> 5;   // 0..4095
        const float4* r = reinterpret_cast<const float4*>(x + (size_t)gw * K_TOTAL);
        float4 f0 = r[lane * 2];
        float4 f1 = r[lane * 2 + 1];
        float s = f0.x * f0.x + f0.y * f0.y + f0.z * f0.z + f0.w * f0.w
                + f1.x * f1.x + f1.y * f1.y + f1.z * f1.z + f1.w * f1.w;
        uint4 v;
        v.x = pack_bf2(f0.x, f0.y);
        v.y = pack_bf2(f0.z, f0.w);
        v.z = pack_bf2(f1.x, f1.y);
        v.w = pack_bf2(f1.z, f1.w);
        *reinterpret_cast<uint4*>(g_xb + (size_t)gw * K_TOTAL + lane * 8) = v;
        #pragma unroll
        for (int o = 16; o; o >>= 1) s += __shfl_xor_sync(0xFFFFFFFFu, s, o);
        if (lane == 0) g_x0[gw] = sqrtf(1.0f + s);
    } else {
        int gw = ((blockIdx.x - 512) * 256 + threadIdx.x) >> 5;  // 0..31999
        const float* r = w + (size_t)gw * 257 + 1 + lane * 8;
        float a0 = r[0], a1 = r[1], a2 = r[2], a3 = r[3];
        float a4 = r[4], a5 = r[5], a6 = r[6], a7 = r[7];
        float s = a0 * a0 + a1 * a1 + a2 * a2 + a3 * a3
                + a4 * a4 + a5 * a5 + a6 * a6 + a7 * a7;
        uint4 v;
        v.x = pack_bf2(a0, a1);
        v.y = pack_bf2(a2, a3);
        v.z = pack_bf2(a4, a5);
        v.w = pack_bf2(a6, a7);
        *reinterpret_cast<uint4*>(g_wb + (size_t)gw * K_TOTAL + lane * 8) = v;
        #pragma unroll
        for (int o = 16; o; o >>= 1) s += __shfl_xor_sync(0xFFFFFFFFu, s, o);
        if (lane == 0) g_c0[gw] = sqrtf(1.0f + s);
    }
}

// ---------------------------------------------------------------------------
// GEMM helpers
// ---------------------------------------------------------------------------
DEV_INLINE float neg_acosh_clip(float v) {
    v = fmaxf(v, 1.0f + 1e-6f);
    float t = fmaf(v, v, -1.0f);
    float s;
    asm("sqrt.approx.f32 %0, %1;" : "=f"(s) : "f"(t));
    float w = v + s;
    float l;
    asm("lg2.approx.f32 %0, %1;" : "=f"(l) : "f"(w));
    return l * -0.6931471805599453f;   // -ln(w)
}

// load A+B chunk kc into pipeline slot `slot` (one cp.async group's worth)
DEV_INLINE void load_chunk(uint32_t sb, int slot, int m_base, int n_base, int kc,
                           int tid) {
    const uint32_t abase = sb + slot * SMEM_SLOT;
    const uint32_t bbase = abase + SMEM_B_OFF;
    const size_t koff = (size_t)kc * KC;
    #pragma unroll
    for (int it = 0; it < 4; it++) {
        int idx = tid + it * 256;      // 0..1023
        int row = idx >> 3;            // 0..127
        int c16 = idx & 7;             // 16B column within 128B row
        uint32_t col = (uint32_t)(c16 * 16) ^ (uint32_t)((row & 7) << 4);
        cp_async16(abase + row * 128 + col,
                   g_xb + (size_t)(m_base + row) * K_TOTAL + koff + c16 * 8);
    }
    #pragma unroll
    for (int it = 0; it < 4; it++) {
        int idx = tid + it * 256;
        int row = idx >> 3;
        int c16 = idx & 7;
        uint32_t col = (uint32_t)(c16 * 16) ^ (uint32_t)((row & 7) << 4);
        cp_async16(bbase + row * 128 + col,
                   g_wb + (size_t)(n_base + row) * K_TOTAL + koff + c16 * 8);
    }
}

struct MmaCtx {
    int a_row; uint32_t a_khalf;
    int b_row; uint32_t b_khalf;
    uint32_t rsw;
};

DEV_INLINE void mma_chunk(uint32_t sb, int slot, const MmaCtx& c,
                          float acc[2][8][4]) {
    const uint32_t abase = sb + slot * SMEM_SLOT;
    const uint32_t bbase = abase + SMEM_B_OFF;
    #pragma unroll
    for (int ks = 0; ks < 4; ks++) {
        const uint32_t kbyte = (uint32_t)(ks * 32);
        uint32_t a[2][4];
        #pragma unroll
        for (int mf = 0; mf < 2; mf++) {
            uint32_t addr = abase + (uint32_t)(c.a_row + mf * 16) * 128 +
                            ((kbyte + c.a_khalf) ^ c.rsw);
            ldmatrix_x4(a[mf][0], a[mf][1], a[mf][2], a[mf][3], addr);
        }
        #pragma unroll
        for (int nf2 = 0; nf2 < 4; nf2++) {
            uint32_t b0, b1, b2, b3;
            uint32_t addr = bbase + (uint32_t)(c.b_row + nf2 * 16) * 128 +
                            ((kbyte + c.b_khalf) ^ c.rsw);
            ldmatrix_x4(b0, b1, b2, b3, addr);
            #pragma unroll
            for (int mf = 0; mf < 2; mf++) {
                mma_16816(acc[mf][nf2 * 2 + 0], a[mf], b0, b1);
                mma_16816(acc[mf][nf2 * 2 + 1], a[mf], b2, b3);
            }
        }
    }
}

// ---------------------------------------------------------------------------
// Main GEMM + arccosh epilogue.
// grid = (250, 32), block = 256 (8 warps; warp tile 32x64: 4 M x 2 N).
// 3-slot cp.async pipeline, one __syncthreads per chunk.
// Epilogue: MUFU acosh in regs -> smem stage (swizzled, conflict-free) ->
// fully coalesced float4 streaming stores (512B per warp instruction).
// ---------------------------------------------------------------------------
__global__ void __launch_bounds__(256, 2) lorentz_gemm_kernel(float* __restrict__ out) {
    extern __shared__ char smem[];
    const uint32_t sb = smem_to_u32(smem);
    const int tid = threadIdx.x;
    const int wid = tid >> 5;
    const int lid = tid & 31;
    const int m_base = blockIdx.y * TM;
    const int n_base = blockIdx.x * TN;

    // warp tile position: 4 warps along M, 2 along N
    const int m_off = (wid & 3) * 32;
    const int n_off = (wid >> 2) * 64;

    // ldmatrix lane decomposition
    const int g = lid >> 3;
    const int r = lid & 7;
    MmaCtx c;
    c.rsw = (uint32_t)(r << 4);
    c.a_row = m_off + (g & 1) * 8 + r;
    c.a_khalf = (uint32_t)((g >> 1) * 16);
    c.b_row = n_off + (g >> 1) * 8 + r;
    c.b_khalf = (uint32_t)((g & 1) * 16);

    float* const s_c0 = reinterpret_cast<float*>(smem + SMEM_C0);
    float* const s_x0 = reinterpret_cast<float*>(smem + SMEM_X0);

    // prologue: chunks 0,1 into slots 0,1
    load_chunk(sb, 0, m_base, n_base, 0, tid);
    cp_async_commit();
    load_chunk(sb, 1, m_base, n_base, 1, tid);
    cp_async_commit();

    if (tid < 128) s_c0[tid] = g_c0[n_base + tid];
    else           s_x0[tid - 128] = g_x0[m_base + tid - 128];

    float acc[2][8][4] = {};

    // iter 0: consume slot 0, issue chunk 2 -> slot 2
    cp_async_wait<1>();
    __syncthreads();
    load_chunk(sb, 2, m_base, n_base, 2, tid);
    cp_async_commit();
    mma_chunk(sb, 0, c, acc);

    // iter 1: consume slot 1, issue chunk 3 -> slot 0 (freed at iter 0)
    cp_async_wait<1>();
    __syncthreads();
    load_chunk(sb, 0, m_base, n_base, 3, tid);
    cp_async_commit();
    mma_chunk(sb, 1, c, acc);

    // iter 2: consume slot 2
    cp_async_wait<1>();
    __syncthreads();
    mma_chunk(sb, 2, c, acc);

    // iter 3: consume slot 0
    cp_async_wait<0>();
    __syncthreads();
    mma_chunk(sb, 0, c, acc);

    // all warps done reading smem tiles before staging overwrites slots 0/1
    __syncthreads();

    // ---- epilogue phase A: MUFU acosh in regs, stage into swizzled smem ----
    // layout: word index = row*128 + (col ^ ((row&7)<<3))   (64KB total)
    float* const s_out = reinterpret_cast<float*>(smem);
    const int tr = lid >> 2;          // 0..7
    const int tc = (lid & 3) * 2;     // 0,2,4,6
    const uint32_t rxor = (uint32_t)((tr & 7) << 3);  // same for row and row+8

    #pragma unroll
    for (int mf = 0; mf < 2; mf++) {
        const int rl = m_off + mf * 16 + tr;
        const float x0a = s_x0[rl];
        const float x0b = s_x0[rl + 8];
        #pragma unroll
        for (int nf = 0; nf < 8; nf++) {
            const int col = n_off + nf * 8 + tc;
            const float c0x = s_c0[col];
            const float c0y = s_c0[col + 1];
            const float* a4 = acc[mf][nf];
            float2 lo, hi;
            lo.x = neg_acosh_clip(fmaf(x0a, c0x, -a4[0]));
            lo.y = neg_acosh_clip(fmaf(x0a, c0y, -a4[1]));
            hi.x = neg_acosh_clip(fmaf(x0b, c0x, -a4[2]));
            hi.y = neg_acosh_clip(fmaf(x0b, c0y, -a4[3]));
            const uint32_t scol = (uint32_t)col ^ rxor;
            *reinterpret_cast<float2*>(s_out + rl * 128 + scol) = lo;
            *reinterpret_cast<float2*>(s_out + (rl + 8) * 128 + scol) = hi;
        }
    }

    __syncthreads();

    // ---- epilogue phase B: coalesced copy smem -> global (float4, 512B/warp) ----
    {
        const uint32_t col4 = (uint32_t)(lid * 4);
        #pragma unroll
        for (int p = 0; p < 16; p++) {
            const int row = p * 8 + wid;
            const uint32_t scol = col4 ^ (uint32_t)((row & 7) << 3);
            float4 v = *reinterpret_cast<const float4*>(s_out + row * 128 + scol);
            __stcs(reinterpret_cast<float4*>(
                       out + (size_t)(m_base + row) * N_TOTAL + n_base + col4), v);
        }
    }
}

// ---------------------------------------------------------------------------
// Launch
// ---------------------------------------------------------------------------
extern "C" void kernel_launch(void* const* d_in, const int* in_sizes, int n_in,
                              void* d_out, int out_size) {
    const float* x = (const float*)d_in[0];        // [2,2048,256] fp32
    const float* w = (const float*)d_in[1];        // [32000,257] fp32
    float* out = (float*)d_out;                    // [2,2048,32000] fp32
    (void)in_sizes; (void)n_in; (void)out_size;

    cudaFuncSetAttribute(lorentz_gemm_kernel,
                         cudaFuncAttributeMaxDynamicSharedMemorySize, SMEM_TOTAL);

    prep_kernel<<<4512, 256>>>(x, w);

    dim3 grid(N_TOTAL / TN, M_TOTAL / TM);  // (250, 32)
    lorentz_gemm_kernel<<<grid, 256, SMEM_TOTAL>>>(out);
}

// round 7
// speedup vs baseline: 1.1650x; 1.1131x over previous
#include <cuda_runtime.h>
#include <cuda_bf16.h>
#include <cstdint>

#define DEV_INLINE __device__ __forceinline__

// ---------------------------------------------------------------------------
// Problem constants
// ---------------------------------------------------------------------------
constexpr int M_TOTAL = 4096;    // B*T
constexpr int N_TOTAL = 32000;   // C
constexpr int K_TOTAL = 256;     // D

constexpr int TM = 64;
constexpr int TN = 128;
constexpr int KC = 64;                        // K chunk (bf16 elems)
constexpr int NKC = K_TOTAL / KC;             // 4 chunks

// smem: 2 pipeline slots, each = A chunk (8KB) + B chunk (16KB) = 24KB
constexpr int SMEM_SLOT   = 24576;
constexpr int SMEM_B_OFF  = 8192;
constexpr int SMEM_C0     = 2 * SMEM_SLOT;            // 49152: 128 floats
constexpr int SMEM_X0     = SMEM_C0 + 512;            // 49664: 64 floats
constexpr int SMEM_TOTAL  = SMEM_X0 + 256;            // 49920 bytes  (x4 = 199680)

// ---------------------------------------------------------------------------
// Scratch (device globals: allocation-free rule)
// ---------------------------------------------------------------------------
__device__ __nv_bfloat16 g_xb[(size_t)M_TOTAL * K_TOTAL];  // 2 MB
__device__ float         g_x0[M_TOTAL];
__device__ __nv_bfloat16 g_wb[(size_t)N_TOTAL * K_TOTAL];  // 16 MB
__device__ float         g_c0[N_TOTAL];

// ---------------------------------------------------------------------------
// PTX helpers (base sm_103-safe: cp.async / ldmatrix / mma.sync only)
// ---------------------------------------------------------------------------
DEV_INLINE uint32_t smem_to_u32(const void* smem_ptr) {
    uint32_t addr;
    asm("{ .reg .u64 tmp; cvta.to.shared.u64 tmp, %1; cvt.u32.u64 %0, tmp; }"
        : "=r"(addr) : "l"(smem_ptr));
    return addr;
}

DEV_INLINE void cp_async16(uint32_t dst_smem, const void* src) {
    asm volatile("cp.async.cg.shared.global [%0], [%1], 16;"
                 :: "r"(dst_smem), "l"(src));
}
DEV_INLINE void cp_async_commit() {
    asm volatile("cp.async.commit_group;" ::: "memory");
}
template <int N>
DEV_INLINE void cp_async_wait() {
    asm volatile("cp.async.wait_group %0;" :: "n"(N) : "memory");
}

DEV_INLINE void ldmatrix_x4(uint32_t& r0, uint32_t& r1, uint32_t& r2, uint32_t& r3,
                            uint32_t addr) {
    asm volatile("ldmatrix.sync.aligned.m8n8.x4.shared.b16 {%0,%1,%2,%3}, [%4];"
                 : "=r"(r0), "=r"(r1), "=r"(r2), "=r"(r3) : "r"(addr));
}

DEV_INLINE void mma_16816(float* d, const uint32_t* a, uint32_t b0, uint32_t b1) {
    asm volatile(
        "mma.sync.aligned.m16n8k16.row.col.f32.bf16.bf16.f32 "
        "{%0,%1,%2,%3}, {%4,%5,%6,%7}, {%8,%9}, {%0,%1,%2,%3};"
        : "+f"(d[0]), "+f"(d[1]), "+f"(d[2]), "+f"(d[3])
        : "r"(a[0]), "r"(a[1]), "r"(a[2]), "r"(a[3]), "r"(b0), "r"(b1));
}

// ---------------------------------------------------------------------------
// Prep kernel (merged): fp32 -> bf16 + exact fp32 Lorentz norms
// blocks [0, 512): x rows (8 rows/block); blocks [512, 4512): w rows
// ---------------------------------------------------------------------------
DEV_INLINE uint32_t pack_bf2(float a, float b) {
    __nv_bfloat162 h = __floats2bfloat162_rn(a, b);
    return *reinterpret_cast<uint32_t*>(&h);
}

__global__ void __launch_bounds__(256) prep_kernel(const float* __restrict__ x,
                                                   const float* __restrict__ w) {
    const int lane = threadIdx.x & 31;
    if (blockIdx.x < 512) {
        int gw = (blockIdx.x * 256 + threadIdx.x) >> 5;   // 0..4095
        const float4* r = reinterpret_cast<const float4*>(x + (size_t)gw * K_TOTAL);
        float4 f0 = r[lane * 2];
        float4 f1 = r[lane * 2 + 1];
        float s = f0.x * f0.x + f0.y * f0.y + f0.z * f0.z + f0.w * f0.w
                + f1.x * f1.x + f1.y * f1.y + f1.z * f1.z + f1.w * f1.w;
        uint4 v;
        v.x = pack_bf2(f0.x, f0.y);
        v.y = pack_bf2(f0.z, f0.w);
        v.z = pack_bf2(f1.x, f1.y);
        v.w = pack_bf2(f1.z, f1.w);
        *reinterpret_cast<uint4*>(g_xb + (size_t)gw * K_TOTAL + lane * 8) = v;
        #pragma unroll
        for (int o = 16; o; o >>= 1) s += __shfl_xor_sync(0xFFFFFFFFu, s, o);
        if (lane == 0) g_x0[gw] = sqrtf(1.0f + s);
    } else {
        int gw = ((blockIdx.x - 512) * 256 + threadIdx.x) >> 5;  // 0..31999
        const float* r = w + (size_t)gw * 257 + 1 + lane * 8;
        float a0 = r[0], a1 = r[1], a2 = r[2], a3 = r[3];
        float a4 = r[4], a5 = r[5], a6 = r[6], a7 = r[7];
        float s = a0 * a0 + a1 * a1 + a2 * a2 + a3 * a3
                + a4 * a4 + a5 * a5 + a6 * a6 + a7 * a7;
        uint4 v;
        v.x = pack_bf2(a0, a1);
        v.y = pack_bf2(a2, a3);
        v.z = pack_bf2(a4, a5);
        v.w = pack_bf2(a6, a7);
        *reinterpret_cast<uint4*>(g_wb + (size_t)gw * K_TOTAL + lane * 8) = v;
        #pragma unroll
        for (int o = 16; o; o >>= 1) s += __shfl_xor_sync(0xFFFFFFFFu, s, o);
        if (lane == 0) g_c0[gw] = sqrtf(1.0f + s);
    }
}

// ---------------------------------------------------------------------------
// GEMM helpers
// ---------------------------------------------------------------------------
DEV_INLINE float neg_acosh_clip(float v) {
    v = fmaxf(v, 1.0f + 1e-6f);
    float t = fmaf(v, v, -1.0f);
    float s;
    asm("sqrt.approx.f32 %0, %1;" : "=f"(s) : "f"(t));
    float w = v + s;
    float l;
    asm("lg2.approx.f32 %0, %1;" : "=f"(l) : "f"(w));
    return l * -0.6931471805599453f;   // -ln(w)
}

// load A (64x64) + B (128x64) chunk kc into pipeline slot `slot` (128 threads)
DEV_INLINE void load_chunk(uint32_t sb, int slot, int m_base, int n_base, int kc,
                           int tid) {
    const uint32_t abase = sb + slot * SMEM_SLOT;
    const uint32_t bbase = abase + SMEM_B_OFF;
    const size_t koff = (size_t)kc * KC;
    #pragma unroll
    for (int it = 0; it < 4; it++) {
        int idx = tid + it * 128;      // 0..511 (64 rows x 8 granules)
        int row = idx >> 3;
        int c16 = idx & 7;
        uint32_t col = (uint32_t)(c16 * 16) ^ (uint32_t)((row & 7) << 4);
        cp_async16(abase + row * 128 + col,
                   g_xb + (size_t)(m_base + row) * K_TOTAL + koff + c16 * 8);
    }
    #pragma unroll
    for (int it = 0; it < 8; it++) {
        int idx = tid + it * 128;      // 0..1023 (128 rows x 8 granules)
        int row = idx >> 3;
        int c16 = idx & 7;
        uint32_t col = (uint32_t)(c16 * 16) ^ (uint32_t)((row & 7) << 4);
        cp_async16(bbase + row * 128 + col,
                   g_wb + (size_t)(n_base + row) * K_TOTAL + koff + c16 * 8);
    }
}

struct MmaCtx {
    int a_row; uint32_t a_khalf;
    int b_row; uint32_t b_khalf;
    uint32_t rsw;
};

DEV_INLINE void mma_chunk(uint32_t sb, int slot, const MmaCtx& c,
                          float acc[2][8][4]) {
    const uint32_t abase = sb + slot * SMEM_SLOT;
    const uint32_t bbase = abase + SMEM_B_OFF;
    #pragma unroll
    for (int ks = 0; ks < 4; ks++) {
        const uint32_t kbyte = (uint32_t)(ks * 32);
        uint32_t a[2][4];
        #pragma unroll
        for (int mf = 0; mf < 2; mf++) {
            uint32_t addr = abase + (uint32_t)(c.a_row + mf * 16) * 128 +
                            ((kbyte + c.a_khalf) ^ c.rsw);
            ldmatrix_x4(a[mf][0], a[mf][1], a[mf][2], a[mf][3], addr);
        }
        #pragma unroll
        for (int nf2 = 0; nf2 < 4; nf2++) {
            uint32_t b0, b1, b2, b3;
            uint32_t addr = bbase + (uint32_t)(c.b_row + nf2 * 16) * 128 +
                            ((kbyte + c.b_khalf) ^ c.rsw);
            ldmatrix_x4(b0, b1, b2, b3, addr);
            #pragma unroll
            for (int mf = 0; mf < 2; mf++) {
                mma_16816(acc[mf][nf2 * 2 + 0], a[mf], b0, b1);
                mma_16816(acc[mf][nf2 * 2 + 1], a[mf], b2, b3);
            }
        }
    }
}

// ---------------------------------------------------------------------------
// Main GEMM + arccosh epilogue.
// grid = (250, 64), block = 128 (4 warps as 2M x 2N; warp tile 32x64).
// 2-slot cp.async pipeline; 4 CTAs/SM (4 independent barrier domains).
// ---------------------------------------------------------------------------
__global__ void __launch_bounds__(128, 4) lorentz_gemm_kernel(float* __restrict__ out) {
    extern __shared__ char smem[];
    const uint32_t sb = smem_to_u32(smem);
    const int tid = threadIdx.x;
    const int wid = tid >> 5;
    const int lid = tid & 31;
    const int m_base = blockIdx.y * TM;
    const int n_base = blockIdx.x * TN;

    // warp tile position: 2 warps along M, 2 along N
    const int m_off = (wid & 1) * 32;
    const int n_off = (wid >> 1) * 64;

    // ldmatrix lane decomposition
    const int g = lid >> 3;
    const int r = lid & 7;
    MmaCtx c;
    c.rsw = (uint32_t)(r << 4);
    c.a_row = m_off + (g & 1) * 8 + r;
    c.a_khalf = (uint32_t)((g >> 1) * 16);
    c.b_row = n_off + (g >> 1) * 8 + r;
    c.b_khalf = (uint32_t)((g & 1) * 16);

    float* const s_c0 = reinterpret_cast<float*>(smem + SMEM_C0);
    float* const s_x0 = reinterpret_cast<float*>(smem + SMEM_X0);

    // prologue: chunks 0,1 into slots 0,1
    load_chunk(sb, 0, m_base, n_base, 0, tid);
    cp_async_commit();
    load_chunk(sb, 1, m_base, n_base, 1, tid);
    cp_async_commit();

    s_c0[tid] = g_c0[n_base + tid];
    if (tid < 64) s_x0[tid] = g_x0[m_base + tid];

    float acc[2][8][4] = {};

    // kc=0: consume slot 0, then refill it with chunk 2
    cp_async_wait<1>();
    __syncthreads();
    mma_chunk(sb, 0, c, acc);
    __syncthreads();
    load_chunk(sb, 0, m_base, n_base, 2, tid);
    cp_async_commit();

    // kc=1: consume slot 1, then refill it with chunk 3
    cp_async_wait<1>();
    __syncthreads();
    mma_chunk(sb, 1, c, acc);
    __syncthreads();
    load_chunk(sb, 1, m_base, n_base, 3, tid);
    cp_async_commit();

    // kc=2: consume slot 0
    cp_async_wait<1>();
    __syncthreads();
    mma_chunk(sb, 0, c, acc);

    // kc=3: consume slot 1
    cp_async_wait<0>();
    __syncthreads();
    mma_chunk(sb, 1, c, acc);

    // ---- epilogue (streaming stores, MUFU acosh) ----
    const int tr = lid >> 2;
    const int tc = (lid & 3) * 2;

    #pragma unroll
    for (int mf = 0; mf < 2; mf++) {
        const int rl = m_off + mf * 16 + tr;
        const float x0a = s_x0[rl];
        const float x0b = s_x0[rl + 8];
        float* out_lo = out + (size_t)(m_base + rl) * N_TOTAL + n_base;
        float* out_hi = out_lo + (size_t)8 * N_TOTAL;
        #pragma unroll
        for (int nf = 0; nf < 8; nf++) {
            const int col = n_off + nf * 8 + tc;
            const float c0x = s_c0[col];
            const float c0y = s_c0[col + 1];
            const float* a4 = acc[mf][nf];
            float2 lo, hi;
            lo.x = neg_acosh_clip(fmaf(x0a, c0x, -a4[0]));
            lo.y = neg_acosh_clip(fmaf(x0a, c0y, -a4[1]));
            hi.x = neg_acosh_clip(fmaf(x0b, c0x, -a4[2]));
            hi.y = neg_acosh_clip(fmaf(x0b, c0y, -a4[3]));
            __stcs(reinterpret_cast<float2*>(out_lo + col), lo);
            __stcs(reinterpret_cast<float2*>(out_hi + col), hi);
        }
    }
}

// ---------------------------------------------------------------------------
// Launch
// ---------------------------------------------------------------------------
extern "C" void kernel_launch(void* const* d_in, const int* in_sizes, int n_in,
                              void* d_out, int out_size) {
    const float* x = (const float*)d_in[0];        // [2,2048,256] fp32
    const float* w = (const float*)d_in[1];        // [32000,257] fp32
    float* out = (float*)d_out;                    // [2,2048,32000] fp32
    (void)in_sizes; (void)n_in; (void)out_size;

    cudaFuncSetAttribute(lorentz_gemm_kernel,
                         cudaFuncAttributeMaxDynamicSharedMemorySize, SMEM_TOTAL);

    prep_kernel<<<4512, 256>>>(x, w);

    dim3 grid(N_TOTAL / TN, M_TOTAL / TM);  // (250, 64)
    lorentz_gemm_kernel<<<grid, 128, SMEM_TOTAL>>>(out);
}